// round 15
// baseline (speedup 1.0000x reference)
#include <cuda_runtime.h>
#include <cuda_bf16.h>
#include <cstdint>

// Problem constants
#define BB    32
#define DD    384
#define TTOT  4096
#define TTILE 64
#define NTHR  256
#define KK    256
#define KC    64
#define NCHK  6
#define TAU   2.0f
#define MAXF  65536
#define NPART 2048

#define Q_ELEMS   ((size_t)BB * DD * TTOT)
#define IDX_ELEMS ((size_t)BB * TTOT)

// SMEM layout (bytes)
#define A_OFF     0        // z bf16 hi, rows=t(64) x 128B, swizzled (8K)
#define B_OFF     8192     // cb bf16 hi chunk (32K)
#define ES_OFF    40960    // e2 [256] f32
#define REDV_OFF  41984    // [64][4] f32
#define REDK_OFF  43008    // [64][4] i32
#define BV_OFF    44032    // [64] f32
#define BK_OFF    44288    // [64] i32
#define CC_OFF    44544    // [64] i32
#define CL_OFF    44800    // [64][7] i32
#define LRED_OFF  46592    // [256] f32
#define SMEM_SZ   47616    // occ 2 @ 256 thr

// Scratch
__device__ float  g_ct[DD * KK];
__device__ float  g_e2f[KK];
__device__ int    g_idx[BB * TTOT];
__device__ float  g_partials[NPART];
__device__ int    g_nflag;
__device__ int    g_fpt[MAXF];
__device__ int    g_fcnt[MAXF];
__device__ int    g_fold[MAXF];         // screening-best index at flag time
__device__ float  g_fsv[MAXF];          // screening-best score (sans x2) at flag time
__device__ int    g_fcand[MAXF][8];
__device__ float  g_ldelta[MAXF];
__device__ unsigned short g_bswh[NCHK * KK * KC];  // pre-swizzled bf16 codebook hi

static __device__ __forceinline__ uint32_t smem_u32(const void* p) {
    uint32_t a;
    asm("{ .reg .u64 t; cvta.to.shared.u64 t, %1; cvt.u32.u64 %0, t; }"
        : "=r"(a) : "l"(p));
    return a;
}

#define CPASYNC16(dst, src) \
    asm volatile("cp.async.cg.shared.global [%0], [%1], 16;" \
        :: "r"(dst), "l"(src) : "memory")
#define CPCOMMIT  asm volatile("cp.async.commit_group;" ::: "memory")
#define CPWAIT0   asm volatile("cp.async.wait_group 0;" ::: "memory")

#define LDSM4(r, ad) \
    asm volatile("ldmatrix.sync.aligned.m8n8.x4.shared.b16 {%0,%1,%2,%3}, [%4];" \
        : "=r"((r)[0]), "=r"((r)[1]), "=r"((r)[2]), "=r"((r)[3]) : "r"(ad))

#define MMA16816(d, a, b0, b1) \
    asm volatile("mma.sync.aligned.m16n8k16.row.col.f32.bf16.bf16.f32 " \
        "{%0,%1,%2,%3},{%4,%5,%6,%7},{%8,%9},{%0,%1,%2,%3};" \
        : "+f"((d)[0]), "+f"((d)[1]), "+f"((d)[2]), "+f"((d)[3]) \
        : "r"((a)[0]), "r"((a)[1]), "r"((a)[2]), "r"((a)[3]), "r"(b0), "r"(b1))

// ---- prep: g_ct transpose + XLA-emulated e2 + bf16 swizzled codebook-hi + reset ----
__global__ void vq_prep(const float* __restrict__ cb) {
    const unsigned FULL = 0xffffffffu;
    int bid = blockIdx.x;
    if (bid < 384) {
        int gid = bid * 256 + threadIdx.x;
        int k = gid / DD;
        int d = gid - k * DD;
        g_ct[d * KK + k] = cb[gid];
    } else if (bid < 416) {
        int lane = threadIdx.x & 31;
        int warp = threadIdx.x >> 5;
        int row = (bid - 384) * 8 + warp;
        const float* c = cb + (size_t)row * DD;
        float s = 0.f;
#pragma unroll
        for (int j = 0; j < DD / 32; ++j) {
            float v = c[lane + 32 * j];
            s = fmaf(v, v, s);
        }
#pragma unroll
        for (int off = 16; off; off >>= 1) s += __shfl_down_sync(FULL, s, off);
        if (lane == 0) g_e2f[row] = s;
    } else if (bid < 800) {
        int gid = (bid - 416) * 256 + threadIdx.x;   // < 98304
        int k = gid / DD;
        int d = gid - k * DD;
        float x = cb[gid];
        __nv_bfloat16 h = __float2bfloat16(x);
        int c   = d >> 6;
        int din = d & 63;
        int idx16 = c * (KK * KC) + k * KC
                  + ((((unsigned)(din * 2)) ^ ((unsigned)(k & 7) * 16)) >> 1);
        g_bswh[idx16] = __bfloat16_as_ushort(h);
    } else {
        if (threadIdx.x == 0) g_nflag = 0;
    }
}

// ---- main: 1-term bf16 mma.sync screening + fused quantize/index write ----
__global__ __launch_bounds__(NTHR, 2) void vq_main(const float* __restrict__ z,
                                                   float* __restrict__ out) {
    extern __shared__ char smem[];
    const uint32_t sb = smem_u32(smem);
    const int tid  = threadIdx.x;
    const int lane = tid & 31;
    const int w    = tid >> 5;
    const int wm   = w & 1;    // t slice (32 t)
    const int wn   = w >> 1;   // code slice (64 codes)
    const int b    = blockIdx.y;
    const int tg   = blockIdx.x * TTILE;

    ((float*)(smem + ES_OFF))[tid] = g_e2f[tid];

    const float* zb = z + (size_t)b * DD * TTOT + tg;
    const int zk = tid >> 4;        // 0..15 -> d = 4*zk + p
    const int zt0 = (tid & 15) * 4; // t0

    float acc[2][8][4];   // [mi][n8 tile][frag]
#pragma unroll
    for (int i = 0; i < 2; ++i)
#pragma unroll
        for (int j = 0; j < 8; ++j)
#pragma unroll
            for (int q = 0; q < 4; ++q) acc[i][j][q] = 0.f;

    float x2acc = 0.f;
    float zr[16];

    // prologue: issue B(0), prefetch z(0) (4 coalesced LDG.128)
    {
        const char* sh = (const char*)(g_bswh);
        uint32_t dh = sb + B_OFF + (unsigned)tid * 16;
#pragma unroll
        for (int j = 0; j < 8; ++j)
            CPASYNC16(dh + 4096u * j, sh + (tid + NTHR * j) * 16);
        CPCOMMIT;
#pragma unroll
        for (int p = 0; p < 4; ++p)
            *(float4*)&zr[p * 4] = *(const float4*)(zb + (size_t)(4 * zk + p) * TTOT + zt0);
    }

    for (int c = 0; c < NCHK; ++c) {
        __syncthreads();    // MMA(c-1) done reading A and B

        if (c > 0) {
            const char* sh = (const char*)(g_bswh + c * (KK * KC));
            uint32_t dh = sb + B_OFF + (unsigned)tid * 16;
#pragma unroll
            for (int j = 0; j < 8; ++j)
                CPASYNC16(dh + 4096u * j, sh + (tid + NTHR * j) * 16);
            CPCOMMIT;
        }

        // convert zr(c) -> A tile (bf16 hi pairs along d, rows=t, swizzled) + x2
#pragma unroll
        for (int jt = 0; jt < 4; ++jt) {
            const int t = zt0 + jt;
            float f0 = zr[jt], f1 = zr[4 + jt];
            float f2 = zr[8 + jt], f3 = zr[12 + jt];
            x2acc = fmaf(f0, f0, fmaf(f1, f1, fmaf(f2, f2, fmaf(f3, f3, x2acc))));
            __nv_bfloat16 h0 = __float2bfloat16(f0), h1 = __float2bfloat16(f1);
            __nv_bfloat16 h2 = __float2bfloat16(f2), h3 = __float2bfloat16(f3);
            unsigned w0 = ((unsigned)__bfloat16_as_ushort(h1) << 16) | __bfloat16_as_ushort(h0);
            unsigned w1 = ((unsigned)__bfloat16_as_ushort(h3) << 16) | __bfloat16_as_ushort(h2);
            const unsigned sw = (unsigned)(t & 7) * 16;
            unsigned off0 = (unsigned)t * 128 + (((unsigned)(8 * zk)) ^ sw);
            unsigned off1 = (unsigned)t * 128 + (((unsigned)(8 * zk + 4)) ^ sw);
            *(unsigned*)(smem + A_OFF + off0) = w0;
            *(unsigned*)(smem + A_OFF + off1) = w1;
        }

        if (c + 1 < NCHK) {
#pragma unroll
            for (int p = 0; p < 4; ++p)
                *(float4*)&zr[p * 4] =
                    *(const float4*)(zb + (size_t)((c + 1) * KC + 4 * zk + p) * TTOT + zt0);
        }

        CPWAIT0;
        __syncthreads();

        // MMA: 4 k16 steps, 1-term
#pragma unroll
        for (int ks = 0; ks < 4; ++ks) {
            uint32_t ah[2][4];
#pragma unroll
            for (int mi = 0; mi < 2; ++mi) {
                int row = wm * 32 + mi * 16 + ((lane >> 3) & 1) * 8 + (lane & 7);
                unsigned kb = (unsigned)ks * 32 + ((lane >> 4) & 1) * 16;
                uint32_t ad = sb + A_OFF + (unsigned)row * 128 + (kb ^ ((unsigned)(row & 7) * 16));
                LDSM4(ah[mi], ad);
            }
#pragma unroll
            for (int ng = 0; ng < 4; ++ng) {
                int n = wn * 64 + ng * 16 + ((lane >> 4) & 1) * 8 + (lane & 7);
                unsigned kb = (unsigned)ks * 32 + ((lane >> 3) & 1) * 16;
                uint32_t bd = sb + B_OFF + (unsigned)n * 128 + (kb ^ ((unsigned)(n & 7) * 16));
                uint32_t bh[4];
                LDSM4(bh, bd);
#pragma unroll
                for (int mi = 0; mi < 2; ++mi) {
#pragma unroll
                    for (int t2 = 0; t2 < 2; ++t2)
                        MMA16816(acc[mi][ng * 2 + t2], ah[mi], bh[t2 * 2], bh[t2 * 2 + 1]);
                }
            }
        }
    }

    // ---- epilogue: argmin over 256 codes ----
    const float* es = (const float*)(smem + ES_OFF);
    float* redv = (float*)(smem + REDV_OFF);
    int*   redk = (int*)(smem + REDK_OFF);
    float* bestv_s = (float*)(smem + BV_OFF);
    int*   bestk_s = (int*)(smem + BK_OFF);
    int*   ccnt = (int*)(smem + CC_OFF);
    int*   clst = (int*)(smem + CL_OFF);
    float* lred = (float*)(smem + LRED_OFF);
    const unsigned FULL = 0xffffffffu;

    float bv[4];
    int   bk[4];
#pragma unroll
    for (int j = 0; j < 4; ++j) { bv[j] = 3.4e38f; bk[j] = KK; }
#pragma unroll
    for (int mi = 0; mi < 2; ++mi)
#pragma unroll
        for (int nt = 0; nt < 8; ++nt)
#pragma unroll
            for (int ci = 0; ci < 4; ++ci) {
                int code = wn * 64 + nt * 8 + (lane & 3) * 2 + (ci & 1);
                int j = mi * 2 + (ci >> 1);
                float sc = es[code] - 2.0f * acc[mi][nt][ci];
                if (sc < bv[j] || (sc == bv[j] && code < bk[j])) { bv[j] = sc; bk[j] = code; }
            }
#pragma unroll
    for (int j = 0; j < 4; ++j) {
#pragma unroll
        for (int off = 1; off < 4; off <<= 1) {
            float ov = __shfl_xor_sync(FULL, bv[j], off);
            int   ok = __shfl_xor_sync(FULL, bk[j], off);
            if (ov < bv[j] || (ov == bv[j] && ok < bk[j])) { bv[j] = ov; bk[j] = ok; }
        }
    }
    if ((lane & 3) == 0) {
#pragma unroll
        for (int j = 0; j < 4; ++j) {
            int t = wm * 32 + (j >> 1) * 16 + (lane >> 2) + (j & 1) * 8;
            redv[t * 4 + wn] = bv[j];
            redk[t * 4 + wn] = bk[j];
        }
    }
    __syncthreads();
    if (tid < TTILE) {
        float fv = redv[tid * 4];
        int   fk = redk[tid * 4];
#pragma unroll
        for (int q = 1; q < 4; ++q) {
            float v = redv[tid * 4 + q];
            int   k = redk[tid * 4 + q];
            if (v < fv || (v == fv && k < fk)) { fv = v; fk = k; }
        }
        bestv_s[tid] = fv;
        bestk_s[tid] = fk;
        ccnt[tid] = 0;
        g_idx[b * TTOT + tg + tid] = fk;
        out[Q_ELEMS + (size_t)b * TTOT + tg + tid] = (float)fk;
    }
    __syncthreads();

    // fused quantize write (screening-best; refine fixes flagged flips later)
    {
        const int wt4 = (tid & 15) * 4;   // 4 consecutive t
        const int wdg = tid >> 4;         // 16 groups x 24 d
        const int k0 = bestk_s[wt4], k1 = bestk_s[wt4 + 1];
        const int k2 = bestk_s[wt4 + 2], k3 = bestk_s[wt4 + 3];
        float* ob = out + (size_t)b * DD * TTOT + tg + wt4;
        const int dlo = wdg * (DD / 16);
#pragma unroll 4
        for (int d = dlo; d < dlo + DD / 16; ++d) {
            const float* row = g_ct + d * KK;
            float4 q = make_float4(row[k0], row[k1], row[k2], row[k3]);
            *(float4*)&ob[(size_t)d * TTOT] = q;
        }
    }

    // candidate scan (score <= best + TAU, code != best)
#pragma unroll
    for (int mi = 0; mi < 2; ++mi)
#pragma unroll
        for (int nt = 0; nt < 8; ++nt)
#pragma unroll
            for (int ci = 0; ci < 4; ++ci) {
                int code = wn * 64 + nt * 8 + (lane & 3) * 2 + (ci & 1);
                int t = wm * 32 + mi * 16 + (lane >> 2) + ((ci >> 1) ? 8 : 0);
                float sc = es[code] - 2.0f * acc[mi][nt][ci];
                if (sc <= bestv_s[t] + TAU && code != bestk_s[t]) {
                    int slot = atomicAdd(&ccnt[t], 1);
                    if (slot < 7) clst[t * 7 + slot] = code;
                }
            }
    __syncthreads();

    if (tid < TTILE && ccnt[tid] > 0) {
        int slot = atomicAdd(&g_nflag, 1);
        if (slot < MAXF) {
            g_fpt[slot] = (b << 12) | (tg + tid);
            g_fold[slot] = bestk_s[tid];
            g_fsv[slot] = bestv_s[tid];
            int cnum = ccnt[tid];
            if (cnum <= 7) {
                g_fcand[slot][0] = bestk_s[tid];
#pragma unroll
                for (int j = 0; j < 7; ++j)
                    if (j < cnum) g_fcand[slot][1 + j] = clst[tid * 7 + j];
                g_fcnt[slot] = cnum + 1;
            } else {
                g_fcnt[slot] = -1;   // scan all 256
            }
        }
    }

    // loss partial: sum x2 + sum best scores
    lred[tid] = x2acc + ((tid < TTILE) ? bestv_s[tid] : 0.f);
    __syncthreads();
    for (int s = NTHR / 2; s > 0; s >>= 1) {
        if (tid < s) lred[tid] += lred[tid + s];
        __syncthreads();
    }
    if (tid == 0) g_partials[b * gridDim.x + blockIdx.x] = lred[0];
}

// ---- refine: exact-emulated re-decision + in-place fixup of flipped points ----
__global__ void vq_refine(const float* __restrict__ z, const float* __restrict__ cb,
                          float* __restrict__ out) {
    const unsigned FULL = 0xffffffffu;
    __shared__ float zsh[4][DD];
    const int lane = threadIdx.x & 31;
    const int warp = threadIdx.x >> 5;
    const int warps_total = gridDim.x * (blockDim.x >> 5);
    const int wg = blockIdx.x * (blockDim.x >> 5) + warp;

    int n = g_nflag;
    if (n > MAXF) n = MAXF;

    for (int e = wg; e < n; e += warps_total) {
        const int pt = g_fpt[e];
        const int b = pt >> 12;
        const int t = pt & 4095;
        const int kold = g_fold[e];
        const float* zp = z + (size_t)b * DD * TTOT + t;

        for (int d = lane; d < DD; d += 32) zsh[warp][d] = zp[(size_t)d * TTOT];
        __syncwarp();

        float s = 0.f;
#pragma unroll
        for (int j = 0; j < DD / 32; ++j) {
            float v = zsh[warp][lane + 32 * j];
            s = fmaf(v, v, s);
        }
#pragma unroll
        for (int off = 16; off; off >>= 1) s += __shfl_down_sync(FULL, s, off);
        const float x2f = __shfl_sync(FULL, s, 0);

        const int cnt = g_fcnt[e];
        const int ncand = (cnt < 0) ? KK : cnt;

        float bestdf = 3.4e38f;
        int bestk = 1 << 30;
        for (int c = lane; c < ncand; c += 32) {
            const int k = (cnt < 0) ? c : g_fcand[e][c];
            const float* ck = cb + (size_t)k * DD;
            float dot = 0.f;
#pragma unroll 8
            for (int d = 0; d < DD; ++d) dot = fmaf(zsh[warp][d], ck[d], dot);
            float df = __fadd_rn(__fsub_rn(x2f, 2.0f * dot), g_e2f[k]);
            if (df < bestdf || (df == bestdf && k < bestk)) { bestdf = df; bestk = k; }
        }
#pragma unroll
        for (int off = 16; off; off >>= 1) {
            float od = __shfl_down_sync(FULL, bestdf, off);
            int   ok = __shfl_down_sync(FULL, bestk, off);
            if (od < bestdf || (od == bestdf && ok < bestk)) { bestdf = od; bestk = ok; }
        }
        bestk = __shfl_sync(FULL, bestk, 0);
        if (lane == 0) {
            g_idx[b * TTOT + t] = bestk;
            g_ldelta[e] = bestdf - (x2f + g_fsv[e]);  // exact dist replaces screen-implied
        }
        // fixup: rewrite quantize row + index float only if the decision flipped
        if (bestk != kold) {
            float* op = out + (size_t)b * DD * TTOT + t;
            for (int d = lane; d < DD; d += 32)
                op[(size_t)d * TTOT] = g_ct[d * KK + bestk];
            if (lane == 0)
                out[Q_ELEMS + (size_t)b * TTOT + t] = (float)bestk;
        }
        __syncwarp();
    }
}

// ---- finalize ----
__global__ void vq_finalize(float* __restrict__ out) {
    __shared__ float s[256];
    int n = g_nflag;
    if (n > MAXF) n = MAXF;
    float a = 0.f;
    for (int j = threadIdx.x; j < NPART; j += 256) a += g_partials[j];
    for (int e = threadIdx.x; e < n; e += 256) a += g_ldelta[e];
    s[threadIdx.x] = a;
    __syncthreads();
    for (int st = 128; st > 0; st >>= 1) {
        if (threadIdx.x < st) s[threadIdx.x] += s[threadIdx.x + st];
        __syncthreads();
    }
    if (threadIdx.x == 0)
        out[Q_ELEMS + IDX_ELEMS] =
            0.25f * s[0] / (float)((size_t)BB * TTOT * DD);
}

extern "C" void kernel_launch(void* const* d_in, const int* in_sizes, int n_in,
                              void* d_out, int out_size) {
    const float* z  = (const float*)d_in[0];
    const float* cb = (const float*)d_in[1];
    float* out = (float*)d_out;

    cudaFuncSetAttribute(vq_main, cudaFuncAttributeMaxDynamicSharedMemorySize, SMEM_SZ);

    vq_prep<<<801, 256>>>(cb);
    dim3 grid(TTOT / TTILE, BB);
    vq_main<<<grid, NTHR, SMEM_SZ>>>(z, out);
    vq_refine<<<1024, 128>>>(z, cb, out);
    vq_finalize<<<1, 256>>>(out);
}

// round 16
// speedup vs baseline: 1.1294x; 1.1294x over previous
#include <cuda_runtime.h>
#include <cuda_bf16.h>
#include <cstdint>

// Problem constants
#define BB    32
#define DD    384
#define TTOT  4096
#define TTILE 64
#define NTHR  256
#define KK    256
#define KC    64
#define NCHK  6
#define TAU   2.0f
#define MAXF  65536
#define NPART 2048

#define Q_ELEMS   ((size_t)BB * DD * TTOT)
#define IDX_ELEMS ((size_t)BB * TTOT)

// SMEM layout (bytes)
#define A0_OFF    0        // z bf16 hi buf0 (8K)
#define A1_OFF    8192     // z bf16 hi buf1 (8K)
#define B0_OFF    16384    // cb bf16 hi buf0 (32K)
#define B1_OFF    49152    // cb bf16 hi buf1 (32K)
#define ES_OFF    81920    // e2 [256] f32
#define REDV_OFF  82944    // [64][4] f32
#define REDK_OFF  83968    // [64][4] i32
#define BV_OFF    84992    // [64] f32
#define BK_OFF    85248    // [64] i32
#define CC_OFF    85504    // [64] i32
#define CL_OFF    85760    // [64][7] i32
#define LRED_OFF  87552    // [256] f32
#define SMEM_SZ   88576    // occ 2 @ 256 thr

// Scratch
__device__ float  g_ct[DD * KK];
__device__ float  g_e2f[KK];
__device__ int    g_idx[BB * TTOT];
__device__ float  g_partials[NPART];
__device__ int    g_nflag;
__device__ int    g_fpt[MAXF];
__device__ int    g_fcnt[MAXF];
__device__ float  g_fsv[MAXF];          // screening-best score (sans x2) at flag time
__device__ int    g_fcand[MAXF][8];
__device__ float  g_ldelta[MAXF];
__device__ unsigned short g_bswh[NCHK * KK * KC];  // pre-swizzled bf16 codebook hi

static __device__ __forceinline__ uint32_t smem_u32(const void* p) {
    uint32_t a;
    asm("{ .reg .u64 t; cvta.to.shared.u64 t, %1; cvt.u32.u64 %0, t; }"
        : "=r"(a) : "l"(p));
    return a;
}

#define CPASYNC16(dst, src) \
    asm volatile("cp.async.cg.shared.global [%0], [%1], 16;" \
        :: "r"(dst), "l"(src) : "memory")
#define CPCOMMIT  asm volatile("cp.async.commit_group;" ::: "memory")
#define CPWAIT0   asm volatile("cp.async.wait_group 0;" ::: "memory")

#define LDSM4(r, ad) \
    asm volatile("ldmatrix.sync.aligned.m8n8.x4.shared.b16 {%0,%1,%2,%3}, [%4];" \
        : "=r"((r)[0]), "=r"((r)[1]), "=r"((r)[2]), "=r"((r)[3]) : "r"(ad))

#define MMA16816(d, a, b0, b1) \
    asm volatile("mma.sync.aligned.m16n8k16.row.col.f32.bf16.bf16.f32 " \
        "{%0,%1,%2,%3},{%4,%5,%6,%7},{%8,%9},{%0,%1,%2,%3};" \
        : "+f"((d)[0]), "+f"((d)[1]), "+f"((d)[2]), "+f"((d)[3]) \
        : "r"((a)[0]), "r"((a)[1]), "r"((a)[2]), "r"((a)[3]), "r"(b0), "r"(b1))

// ---- prep: g_ct transpose + XLA-emulated e2 + bf16 swizzled codebook-hi + reset ----
__global__ void vq_prep(const float* __restrict__ cb) {
    const unsigned FULL = 0xffffffffu;
    int bid = blockIdx.x;
    if (bid < 384) {
        int gid = bid * 256 + threadIdx.x;
        int k = gid / DD;
        int d = gid - k * DD;
        g_ct[d * KK + k] = cb[gid];
    } else if (bid < 416) {
        int lane = threadIdx.x & 31;
        int warp = threadIdx.x >> 5;
        int row = (bid - 384) * 8 + warp;
        const float* c = cb + (size_t)row * DD;
        float s = 0.f;
#pragma unroll
        for (int j = 0; j < DD / 32; ++j) {
            float v = c[lane + 32 * j];
            s = fmaf(v, v, s);
        }
#pragma unroll
        for (int off = 16; off; off >>= 1) s += __shfl_down_sync(FULL, s, off);
        if (lane == 0) g_e2f[row] = s;
    } else if (bid < 800) {
        int gid = (bid - 416) * 256 + threadIdx.x;   // < 98304
        int k = gid / DD;
        int d = gid - k * DD;
        float x = cb[gid];
        __nv_bfloat16 h = __float2bfloat16(x);
        int c   = d >> 6;
        int din = d & 63;
        int idx16 = c * (KK * KC) + k * KC
                  + ((((unsigned)(din * 2)) ^ ((unsigned)(k & 7) * 16)) >> 1);
        g_bswh[idx16] = __bfloat16_as_ushort(h);
    } else {
        if (threadIdx.x == 0) g_nflag = 0;
    }
}

// ---- main: 1-term bf16 mma.sync screening, occ-2, 2-deep A/B pipeline ----
__global__ __launch_bounds__(NTHR, 2) void vq_main(const float* __restrict__ z) {
    extern __shared__ char smem[];
    const uint32_t sb = smem_u32(smem);
    const int tid  = threadIdx.x;
    const int lane = tid & 31;
    const int w    = tid >> 5;
    const int wm   = w & 1;    // t slice (32 t)
    const int wn   = w >> 1;   // code slice (64 codes)
    const int b    = blockIdx.y;
    const int tg   = blockIdx.x * TTILE;

    ((float*)(smem + ES_OFF))[tid] = g_e2f[tid];

    const float* zb = z + (size_t)b * DD * TTOT + tg;
    const int zk = tid >> 4;        // 0..15 -> d = 4*zk + p
    const int zt0 = (tid & 15) * 4; // t0

    const uint32_t abase[2] = { sb + A0_OFF, sb + A1_OFF };
    const uint32_t bbase[2] = { sb + B0_OFF, sb + B1_OFF };

    float acc[2][8][4];   // [mi][n8 tile][frag]
#pragma unroll
    for (int i = 0; i < 2; ++i)
#pragma unroll
        for (int j = 0; j < 8; ++j)
#pragma unroll
            for (int q = 0; q < 4; ++q) acc[i][j][q] = 0.f;

    float x2acc = 0.f;
    float zr[16];

    // convert helper expanded inline below; zr holds the chunk to convert
#define CONVERT_TO_A(abuf)                                                         \
    {                                                                              \
        _Pragma("unroll")                                                          \
        for (int jt = 0; jt < 4; ++jt) {                                           \
            const int t = zt0 + jt;                                                \
            float f0 = zr[jt], f1 = zr[4 + jt];                                    \
            float f2 = zr[8 + jt], f3 = zr[12 + jt];                               \
            x2acc = fmaf(f0, f0, fmaf(f1, f1, fmaf(f2, f2, fmaf(f3, f3, x2acc)))); \
            __nv_bfloat16 h0 = __float2bfloat16(f0), h1 = __float2bfloat16(f1);    \
            __nv_bfloat16 h2 = __float2bfloat16(f2), h3 = __float2bfloat16(f3);    \
            unsigned w0 = ((unsigned)__bfloat16_as_ushort(h1) << 16) | __bfloat16_as_ushort(h0); \
            unsigned w1 = ((unsigned)__bfloat16_as_ushort(h3) << 16) | __bfloat16_as_ushort(h2); \
            const unsigned sw = (unsigned)(t & 7) * 16;                            \
            unsigned off0 = (unsigned)t * 128 + (((unsigned)(8 * zk)) ^ sw);       \
            unsigned off1 = (unsigned)t * 128 + (((unsigned)(8 * zk + 4)) ^ sw);   \
            *(unsigned*)((char*)smem + ((abuf) - sb) + off0) = w0;                 \
            *(unsigned*)((char*)smem + ((abuf) - sb) + off1) = w1;                 \
        }                                                                          \
    }

#define ISSUE_B(c, bbuf)                                                           \
    {                                                                              \
        const char* sh = (const char*)(g_bswh + (c) * (KK * KC));                  \
        uint32_t dh = (bbuf) + (unsigned)tid * 16;                                 \
        _Pragma("unroll")                                                          \
        for (int j = 0; j < 8; ++j)                                                \
            CPASYNC16(dh + 4096u * j, sh + (tid + NTHR * j) * 16);                 \
        CPCOMMIT;                                                                  \
    }

#define LOAD_ZR(c)                                                                 \
    {                                                                              \
        _Pragma("unroll")                                                          \
        for (int p = 0; p < 4; ++p)                                                \
            *(float4*)&zr[p * 4] =                                                 \
                *(const float4*)(zb + (size_t)((c) * KC + 4 * zk + p) * TTOT + zt0); \
    }

    // prologue: B(0) issued; A(0) converted; zr <- z(1); B(0) awaited
    ISSUE_B(0, bbase[0]);
    LOAD_ZR(0);
    CONVERT_TO_A(abase[0]);
    LOAD_ZR(1);
    CPWAIT0;
    __syncthreads();   // A(0), B(0) visible

    for (int c = 0; c < NCHK; ++c) {
        // issue B(c+1) into buffer freed by MMA(c-1) (sync of prev iter protects it)
        if (c + 1 < NCHK) ISSUE_B(c + 1, bbase[(c + 1) & 1]);

        // MMA(c): 4 k16 steps, 1-term
        const uint32_t acur = abase[c & 1];
        const uint32_t bcur = bbase[c & 1];
#pragma unroll
        for (int ks = 0; ks < 4; ++ks) {
            uint32_t ah[2][4];
#pragma unroll
            for (int mi = 0; mi < 2; ++mi) {
                int row = wm * 32 + mi * 16 + ((lane >> 3) & 1) * 8 + (lane & 7);
                unsigned kb = (unsigned)ks * 32 + ((lane >> 4) & 1) * 16;
                uint32_t ad = acur + (unsigned)row * 128 + (kb ^ ((unsigned)(row & 7) * 16));
                LDSM4(ah[mi], ad);
            }
#pragma unroll
            for (int ng = 0; ng < 4; ++ng) {
                int n = wn * 64 + ng * 16 + ((lane >> 4) & 1) * 8 + (lane & 7);
                unsigned kb = (unsigned)ks * 32 + ((lane >> 3) & 1) * 16;
                uint32_t bd = bcur + (unsigned)n * 128 + (kb ^ ((unsigned)(n & 7) * 16));
                uint32_t bh[4];
                LDSM4(bh, bd);
#pragma unroll
                for (int mi = 0; mi < 2; ++mi) {
#pragma unroll
                    for (int t2 = 0; t2 < 2; ++t2)
                        MMA16816(acc[mi][ng * 2 + t2], ah[mi], bh[t2 * 2], bh[t2 * 2 + 1]);
                }
            }
        }

        if (c + 1 < NCHK) {
            // convert zr (= chunk c+1) into alternate A buffer (freed by MMA(c-1))
            CONVERT_TO_A(abase[(c + 1) & 1]);
            if (c + 2 < NCHK) LOAD_ZR(c + 2);
            CPWAIT0;       // B(c+1) done (latency covered by MMA+convert)
        }
        __syncthreads();   // one barrier per chunk
    }

    // ---- epilogue: argmin over 256 codes ----
    const float* es = (const float*)(smem + ES_OFF);
    float* redv = (float*)(smem + REDV_OFF);
    int*   redk = (int*)(smem + REDK_OFF);
    float* bestv_s = (float*)(smem + BV_OFF);
    int*   bestk_s = (int*)(smem + BK_OFF);
    int*   ccnt = (int*)(smem + CC_OFF);
    int*   clst = (int*)(smem + CL_OFF);
    float* lred = (float*)(smem + LRED_OFF);
    const unsigned FULL = 0xffffffffu;

    float bv[4];
    int   bk[4];
#pragma unroll
    for (int j = 0; j < 4; ++j) { bv[j] = 3.4e38f; bk[j] = KK; }
#pragma unroll
    for (int mi = 0; mi < 2; ++mi)
#pragma unroll
        for (int nt = 0; nt < 8; ++nt)
#pragma unroll
            for (int ci = 0; ci < 4; ++ci) {
                int code = wn * 64 + nt * 8 + (lane & 3) * 2 + (ci & 1);
                int j = mi * 2 + (ci >> 1);
                float sc = es[code] - 2.0f * acc[mi][nt][ci];
                if (sc < bv[j] || (sc == bv[j] && code < bk[j])) { bv[j] = sc; bk[j] = code; }
            }
#pragma unroll
    for (int j = 0; j < 4; ++j) {
#pragma unroll
        for (int off = 1; off < 4; off <<= 1) {
            float ov = __shfl_xor_sync(FULL, bv[j], off);
            int   ok = __shfl_xor_sync(FULL, bk[j], off);
            if (ov < bv[j] || (ov == bv[j] && ok < bk[j])) { bv[j] = ov; bk[j] = ok; }
        }
    }
    if ((lane & 3) == 0) {
#pragma unroll
        for (int j = 0; j < 4; ++j) {
            int t = wm * 32 + (j >> 1) * 16 + (lane >> 2) + (j & 1) * 8;
            redv[t * 4 + wn] = bv[j];
            redk[t * 4 + wn] = bk[j];
        }
    }
    __syncthreads();
    if (tid < TTILE) {
        float fv = redv[tid * 4];
        int   fk = redk[tid * 4];
#pragma unroll
        for (int q = 1; q < 4; ++q) {
            float v = redv[tid * 4 + q];
            int   k = redk[tid * 4 + q];
            if (v < fv || (v == fv && k < fk)) { fv = v; fk = k; }
        }
        bestv_s[tid] = fv;
        bestk_s[tid] = fk;
        ccnt[tid] = 0;
        g_idx[b * TTOT + tg + tid] = fk;
    }
    __syncthreads();

    // candidate scan (score <= best + TAU, code != best)
#pragma unroll
    for (int mi = 0; mi < 2; ++mi)
#pragma unroll
        for (int nt = 0; nt < 8; ++nt)
#pragma unroll
            for (int ci = 0; ci < 4; ++ci) {
                int code = wn * 64 + nt * 8 + (lane & 3) * 2 + (ci & 1);
                int t = wm * 32 + mi * 16 + (lane >> 2) + ((ci >> 1) ? 8 : 0);
                float sc = es[code] - 2.0f * acc[mi][nt][ci];
                if (sc <= bestv_s[t] + TAU && code != bestk_s[t]) {
                    int slot = atomicAdd(&ccnt[t], 1);
                    if (slot < 7) clst[t * 7 + slot] = code;
                }
            }
    __syncthreads();

    if (tid < TTILE && ccnt[tid] > 0) {
        int slot = atomicAdd(&g_nflag, 1);
        if (slot < MAXF) {
            g_fpt[slot] = (b << 12) | (tg + tid);
            g_fsv[slot] = bestv_s[tid];
            int cnum = ccnt[tid];
            if (cnum <= 7) {
                g_fcand[slot][0] = bestk_s[tid];
#pragma unroll
                for (int j = 0; j < 7; ++j)
                    if (j < cnum) g_fcand[slot][1 + j] = clst[tid * 7 + j];
                g_fcnt[slot] = cnum + 1;
            } else {
                g_fcnt[slot] = -1;   // scan all 256
            }
        }
    }

    // loss partial: sum x2 + sum best scores
    lred[tid] = x2acc + ((tid < TTILE) ? bestv_s[tid] : 0.f);
    __syncthreads();
    for (int s = NTHR / 2; s > 0; s >>= 1) {
        if (tid < s) lred[tid] += lred[tid + s];
        __syncthreads();
    }
    if (tid == 0) g_partials[b * gridDim.x + blockIdx.x] = lred[0];
#undef CONVERT_TO_A
#undef ISSUE_B
#undef LOAD_ZR
}

// ---- refine: reference-fp32-EMULATED re-decision of flagged points ----
__global__ void vq_refine(const float* __restrict__ z, const float* __restrict__ cb) {
    const unsigned FULL = 0xffffffffu;
    __shared__ float zsh[4][DD];
    const int lane = threadIdx.x & 31;
    const int warp = threadIdx.x >> 5;
    const int warps_total = gridDim.x * (blockDim.x >> 5);
    const int wg = blockIdx.x * (blockDim.x >> 5) + warp;

    int n = g_nflag;
    if (n > MAXF) n = MAXF;

    for (int e = wg; e < n; e += warps_total) {
        const int pt = g_fpt[e];
        const int b = pt >> 12;
        const int t = pt & 4095;
        const float* zp = z + (size_t)b * DD * TTOT + t;

        for (int d = lane; d < DD; d += 32) zsh[warp][d] = zp[(size_t)d * TTOT];
        __syncwarp();

        float s = 0.f;
#pragma unroll
        for (int j = 0; j < DD / 32; ++j) {
            float v = zsh[warp][lane + 32 * j];
            s = fmaf(v, v, s);
        }
#pragma unroll
        for (int off = 16; off; off >>= 1) s += __shfl_down_sync(FULL, s, off);
        const float x2f = __shfl_sync(FULL, s, 0);

        const int cnt = g_fcnt[e];
        const int ncand = (cnt < 0) ? KK : cnt;

        float bestdf = 3.4e38f;
        int bestk = 1 << 30;
        for (int c = lane; c < ncand; c += 32) {
            const int k = (cnt < 0) ? c : g_fcand[e][c];
            const float* ck = cb + (size_t)k * DD;
            float dot = 0.f;
#pragma unroll 8
            for (int d = 0; d < DD; ++d) dot = fmaf(zsh[warp][d], ck[d], dot);
            float df = __fadd_rn(__fsub_rn(x2f, 2.0f * dot), g_e2f[k]);
            if (df < bestdf || (df == bestdf && k < bestk)) { bestdf = df; bestk = k; }
        }
#pragma unroll
        for (int off = 16; off; off >>= 1) {
            float od = __shfl_down_sync(FULL, bestdf, off);
            int   ok = __shfl_down_sync(FULL, bestk, off);
            if (od < bestdf || (od == bestdf && ok < bestk)) { bestdf = od; bestk = ok; }
        }
        if (lane == 0) {
            g_idx[b * TTOT + t] = bestk;
            g_ldelta[e] = bestdf - (x2f + g_fsv[e]);  // exact dist replaces screen-implied
        }
        __syncwarp();
    }
}

// ---- writer: gather-only quantize + indices ----
__global__ __launch_bounds__(256) void vq_write(float* __restrict__ out) {
    const int tid = threadIdx.x;
    const int b  = blockIdx.y;
    const int dz = blockIdx.z;                      // 0..7, 48 d each
    const int t4 = (blockIdx.x * 256 + tid) << 2;

    const int4 kk = *(const int4*)&g_idx[b * TTOT + t4];

    if (dz == 0) {
        float4 fi = make_float4((float)kk.x, (float)kk.y, (float)kk.z, (float)kk.w);
        *(float4*)&out[Q_ELEMS + (size_t)b * TTOT + t4] = fi;
    }

    float* ob = out + (size_t)b * DD * TTOT + t4;
    const int dlo = dz * (DD / 8);
#pragma unroll 4
    for (int d = dlo; d < dlo + DD / 8; ++d) {
        const float* row = g_ct + d * KK;
        float4 q = make_float4(row[kk.x], row[kk.y], row[kk.z], row[kk.w]);
        *(float4*)&ob[(size_t)d * TTOT] = q;
    }
}

// ---- finalize: 1024-thread deterministic reduction ----
__global__ void vq_finalize(float* __restrict__ out) {
    __shared__ float s[1024];
    int n = g_nflag;
    if (n > MAXF) n = MAXF;
    float a = 0.f;
    for (int j = threadIdx.x; j < NPART; j += 1024) a += g_partials[j];
    for (int e = threadIdx.x; e < n; e += 1024) a += g_ldelta[e];
    s[threadIdx.x] = a;
    __syncthreads();
    for (int st = 512; st > 0; st >>= 1) {
        if (threadIdx.x < st) s[threadIdx.x] += s[threadIdx.x + st];
        __syncthreads();
    }
    if (threadIdx.x == 0)
        out[Q_ELEMS + IDX_ELEMS] =
            0.25f * s[0] / (float)((size_t)BB * TTOT * DD);
}

extern "C" void kernel_launch(void* const* d_in, const int* in_sizes, int n_in,
                              void* d_out, int out_size) {
    const float* z  = (const float*)d_in[0];
    const float* cb = (const float*)d_in[1];
    float* out = (float*)d_out;

    cudaFuncSetAttribute(vq_main, cudaFuncAttributeMaxDynamicSharedMemorySize, SMEM_SZ);

    vq_prep<<<801, 256>>>(cb);
    dim3 grid(TTOT / TTILE, BB);
    vq_main<<<grid, NTHR, SMEM_SZ>>>(z);
    vq_refine<<<1024, 128>>>(z, cb);
    dim3 wgrid(TTOT / 1024, BB, 8);
    vq_write<<<wgrid, 256>>>(out);
    vq_finalize<<<1, 1024>>>(out);
}